// round 12
// baseline (speedup 1.0000x reference)
#include <cuda_runtime.h>
#include <math.h>
#include <float.h>

#define H 1024
#define F 2048
#define V 50257
#define NB 148              // all CTAs co-resident: 1 CTA/SM, 148 <= 152 SMs
#define TPB 512             // 16 warps -> 128 regs/thread budget
#define NWARP (NB * 16)     // 2368 warps grid-wide
#define NPAIR ((V + 1) / 2) // 25129 row-pairs in the big GEMV

// ---------------- scratch (device globals; no allocation) ----------------
__device__ float g_attn_logits[F];
__device__ float g_attn_w[F];
__device__ float g_part[NB * H];     // per-block attn partials
__device__ float g_attn_applied[H];
__device__ float g_x[H];
__device__ float g_gx[3 * H];
__device__ float g_gh[3 * H];
__device__ float g_hnew[H];
__device__ float2 g_lsm_part[NB];
__device__ float2 g_lsm_fin;
__device__ unsigned g_bar;           // monotonic grid barrier counter

// ---------------- helpers ----------------
__device__ __forceinline__ float warp_sum(float v) {
#pragma unroll
    for (int o = 16; o; o >>= 1) v += __shfl_xor_sync(0xffffffffu, v, o);
    return v;
}
__device__ __forceinline__ float warp_max(float v) {
#pragma unroll
    for (int o = 16; o; o >>= 1) v = fmaxf(v, __shfl_xor_sync(0xffffffffu, v, o));
    return v;
}
__device__ __forceinline__ float dot4(float4 a, float4 b) {
    return a.x * b.x + a.y * b.y + a.z * b.z + a.w * b.w;
}

// Two H-wide dots with ONE front-batched block of 16 LDG.128 (8 KB/warp in
// flight). Vector operands vA/vB are L1-resident; their loads interleave with
// the FMA chain after the weight batch is issued.
__device__ __forceinline__ float2 dot2_batch(const float4* __restrict__ wA,
                                             const float4* __restrict__ vA,
                                             const float4* __restrict__ wB,
                                             const float4* __restrict__ vB,
                                             int lane) {
    float4 a[8], b[8];
#pragma unroll
    for (int k = 0; k < 8; ++k) a[k] = wA[lane + 32 * k];
#pragma unroll
    for (int k = 0; k < 8; ++k) b[k] = wB[lane + 32 * k];
    float sA = 0.f, sB = 0.f;
#pragma unroll
    for (int k = 0; k < 8; ++k) {
        sA += dot4(a[k], vA[lane + 32 * k]);
        sB += dot4(b[k], vB[lane + 32 * k]);
    }
    return make_float2(sA, sB);
}

// Monotonic phase barrier: counter always left at k*NB => graph-replay safe.
// Bounded spin: never triggers normally; on residency violation we terminate
// (clean test failure) instead of hanging the device.
__device__ __forceinline__ void gsync() {
    __syncthreads();
    __threadfence();
    if (threadIdx.x == 0) {
        unsigned old = atomicAdd(&g_bar, 1);
        unsigned target = (old / NB + 1) * NB;
        long long guard = 0;
        while (*((volatile unsigned*)&g_bar) < target) {
            __nanosleep(32);
            if (++guard > 100000000LL) break;
        }
    }
    __syncthreads();
}

__global__ void __launch_bounds__(TPB, 1)
k_fused(const int* __restrict__ tok, const float* __restrict__ hvec,
        const float* __restrict__ enc, const float* __restrict__ emb,
        const float* __restrict__ attn_W, const float* __restrict__ attn_b,
        const float* __restrict__ comb_W, const float* __restrict__ comb_b,
        const float* __restrict__ W_ih, const float* __restrict__ W_hh,
        const float* __restrict__ b_ih, const float* __restrict__ b_hh,
        const float* __restrict__ out_W, const float* __restrict__ out_b,
        float* __restrict__ out, float* __restrict__ h_out,
        float* __restrict__ attn_w_out)
{
    const int tid  = threadIdx.x;
    const int wid  = tid >> 5;          // 0..15
    const int lane = tid & 31;
    const int gw   = blockIdx.x * 16 + wid;

    const float4* e  = (const float4*)(emb + (size_t)tok[0] * H);
    const float4* hv = (const float4*)hvec;

    // ===== A: attn logits (F rows of 2H, batched both halves)
    //          + gh = W_hh*h + b_hh (3H rows, 2 rows/iter), 28 MB =====
    {
        const int UNITS = F + (3 * H) / 2;   // 2048 + 1536 = 3584 work units
        for (int u = gw; u < UNITS; u += NWARP) {
            if (u < F) {
                const float4* w1 = (const float4*)(attn_W + (size_t)u * (2 * H));
                float2 d = dot2_batch(w1, e, w1 + H / 4, hv, lane);
                float acc = warp_sum(d.x + d.y);
                if (lane == 0) g_attn_logits[u] = acc + attn_b[u];
            } else {
                int p = u - F;                // 0..1535 -> rows 2p, 2p+1
                int r0 = 2 * p;
                const float4* w0 = (const float4*)(W_hh + (size_t)r0 * H);
                float2 d = dot2_batch(w0, hv, w0 + H / 4, hv, lane);
                float a0 = warp_sum(d.x);
                float a1 = warp_sum(d.y);
                if (lane == 0) {
                    g_gh[r0]     = a0 + b_hh[r0];
                    g_gh[r0 + 1] = a1 + b_hh[r0 + 1];
                }
            }
        }
    }
    gsync();

    // ===== B: softmax over F (block 0, 512 threads x 4 elems) =====
    if (blockIdx.x == 0) {
        __shared__ float sh[16];
        float x0 = g_attn_logits[tid],        x1 = g_attn_logits[tid + 512];
        float x2 = g_attn_logits[tid + 1024], x3 = g_attn_logits[tid + 1536];
        float m = fmaxf(fmaxf(x0, x1), fmaxf(x2, x3));
        m = warp_max(m);
        if (lane == 0) sh[wid] = m;
        __syncthreads();
        if (tid < 32) {
            float v = (tid < 16) ? sh[tid] : -FLT_MAX;
            v = warp_max(v);
            if (tid == 0) sh[0] = v;
        }
        __syncthreads();
        m = sh[0];
        __syncthreads();
        float e0 = __expf(x0 - m), e1 = __expf(x1 - m);
        float e2 = __expf(x2 - m), e3 = __expf(x3 - m);
        float s = warp_sum(e0 + e1 + e2 + e3);
        if (lane == 0) sh[wid] = s;
        __syncthreads();
        if (tid < 32) {
            float v = (tid < 16) ? sh[tid] : 0.f;
            v = warp_sum(v);
            if (tid == 0) sh[0] = v;
        }
        __syncthreads();
        float inv = 1.f / sh[0];
        g_attn_w[tid]        = e0 * inv;  attn_w_out[tid]        = e0 * inv;
        g_attn_w[tid + 512]  = e1 * inv;  attn_w_out[tid + 512]  = e1 * inv;
        g_attn_w[tid + 1024] = e2 * inv;  attn_w_out[tid + 1024] = e2 * inv;
        g_attn_w[tid + 1536] = e3 * inv;  attn_w_out[tid + 1536] = e3 * inv;
    }
    gsync();

    // ===== C: attn_applied partials — each block covers 14 f-rows, 8 MB =====
    {
        int f0 = blockIdx.x * 14;
        int nf = F - f0; if (nf > 14) nf = 14; if (nf < 0) nf = 0;
        float acc0 = 0.f, acc1 = 0.f;
        for (int j = 0; j < nf; ++j) {
            float wv = g_attn_w[f0 + j];
            acc0 = fmaf(wv, enc[(size_t)(f0 + j) * H + tid],       acc0);
            acc1 = fmaf(wv, enc[(size_t)(f0 + j) * H + tid + 512], acc1);
        }
        g_part[blockIdx.x * H + tid]       = acc0;
        g_part[blockIdx.x * H + tid + 512] = acc1;
    }
    gsync();

    // ===== D: reduce NB partials (blocks 0-1, one col/thread) =====
    if (blockIdx.x < 2) {
        int c = blockIdx.x * 512 + tid;
        float acc = 0.f;
        for (int p = 0; p < NB; ++p) acc += g_part[p * H + c];
        g_attn_applied[c] = acc;
    }
    gsync();

    // ===== E: combine + relu (H rows of 2H, batched both halves), 8 MB =====
    {
        const float4* av = (const float4*)g_attn_applied;
        for (int r = gw; r < H; r += NWARP) {
            const float4* w1 = (const float4*)(comb_W + (size_t)r * (2 * H));
            float2 d = dot2_batch(w1, e, w1 + H / 4, av, lane);
            float acc = warp_sum(d.x + d.y);
            if (lane == 0) g_x[r] = fmaxf(acc + comb_b[r], 0.f);
        }
    }
    gsync();

    // ===== F: gx = W_ih*x + b_ih (3H rows, 2 rows/iter), 12 MB =====
    {
        const float4* xv = (const float4*)g_x;
        for (int p = gw; p < (3 * H) / 2; p += NWARP) {
            int r0 = 2 * p;
            const float4* w0 = (const float4*)(W_ih + (size_t)r0 * H);
            float2 d = dot2_batch(w0, xv, w0 + H / 4, xv, lane);
            float a0 = warp_sum(d.x);
            float a1 = warp_sum(d.y);
            if (lane == 0) {
                g_gx[r0]     = a0 + b_ih[r0];
                g_gx[r0 + 1] = a1 + b_ih[r0 + 1];
            }
        }
    }
    gsync();

    // ===== G: gates -> h_new (block 0, 2 elems/thread) =====
    if (blockIdx.x == 0) {
#pragma unroll
        for (int k = 0; k < 2; ++k) {
            int i = tid + k * 512;
            float r = 1.f / (1.f + __expf(-(g_gx[i]     + g_gh[i])));
            float z = 1.f / (1.f + __expf(-(g_gx[H + i] + g_gh[H + i])));
            float n = tanhf(g_gx[2 * H + i] + r * g_gh[2 * H + i]);
            float hn = (1.f - z) * n + z * hvec[i];
            g_hnew[i] = hn;
            h_out[i] = hn;                     // scalar store, alignment-safe
        }
    }
    gsync();

    // ===== H: output logits (V rows, 2 rows/iter, one 16-load batch), 206 MB
    //          + fused per-block online (max,sum) for log-softmax =====
    {
        const float4* hn = (const float4*)g_hnew;   // L1-resident vector
        float m = -FLT_MAX, s = 0.f;                // identical across lanes
        for (int p = gw; p < NPAIR; p += NWARP) {
            int r0 = 2 * p;
            int r1 = r0 + 1;
            bool has1 = (r1 < V);
            const float4* w0 = (const float4*)(out_W + (size_t)r0 * H);
            const float4* w1 = (const float4*)(out_W + (size_t)(has1 ? r1 : r0) * H);
            float b0 = out_b[r0];
            float b1 = out_b[has1 ? r1 : r0];
            float2 d = dot2_batch(w0, hn, w1, hn, lane);
            float acc0 = warp_sum(d.x);
            float acc1 = warp_sum(d.y);
            float l0 = acc0 + b0;
            if (lane == 0) out[r0] = l0;
            { float nm = fmaxf(m, l0); s = s * __expf(m - nm) + __expf(l0 - nm); m = nm; }
            if (has1) {
                float l1 = acc1 + b1;
                if (lane == 0) out[r1] = l1;
                float nm = fmaxf(m, l1); s = s * __expf(m - nm) + __expf(l1 - nm); m = nm;
            }
        }
        // block-level combine of 16 per-warp (m,s)
        __shared__ float sma[16], ssa[16];
        if (lane == 0) { sma[wid] = m; ssa[wid] = s; }
        __syncthreads();
        if (tid < 32) {
            float mm = (tid < 16) ? sma[tid] : -FLT_MAX;
            float ss = (tid < 16) ? ssa[tid] : 0.f;
#pragma unroll
            for (int o = 16; o; o >>= 1) {
                float m2 = __shfl_xor_sync(0xffffffffu, mm, o);
                float s2 = __shfl_xor_sync(0xffffffffu, ss, o);
                float nm = fmaxf(mm, m2);
                ss = ss * __expf(mm - nm) + s2 * __expf(m2 - nm);
                mm = nm;
            }
            if (tid == 0) g_lsm_part[blockIdx.x] = make_float2(mm, ss);
        }
    }
    gsync();

    // ===== I: combine NB partials (block 0, warp 0 only — sync-free) =====
    if (blockIdx.x == 0 && wid == 0) {
        float m = -FLT_MAX, s = 0.f;
        for (int i = lane; i < NB; i += 32) {      // fixed per-lane order
            float2 p = g_lsm_part[i];
            float nm = fmaxf(m, p.x);
            s = s * __expf(m - nm) + p.y * __expf(p.x - nm);
            m = nm;
        }
#pragma unroll
        for (int o = 16; o; o >>= 1) {
            float m2 = __shfl_xor_sync(0xffffffffu, m, o);
            float s2 = __shfl_xor_sync(0xffffffffu, s, o);
            float nm = fmaxf(m, m2);
            s = s * __expf(m - nm) + s2 * __expf(m2 - nm);
            m = nm;
        }
        if (lane == 0) g_lsm_fin = make_float2(m, logf(s));
    }
    gsync();

    // ===== J: subtract (one elem/thread; NB*TPB = 75776 >= V) =====
    {
        int v = blockIdx.x * TPB + tid;
        if (v < V) {
            float2 f = g_lsm_fin;
            out[v] = out[v] - f.x - f.y;
        }
    }
}

// ---------------- launcher ----------------
extern "C" void kernel_launch(void* const* d_in, const int* in_sizes, int n_in,
                              void* d_out, int out_size) {
    const int*   tok     = (const int*)  d_in[0];
    const float* hidden  = (const float*)d_in[1];
    const float* enc     = (const float*)d_in[2];
    const float* emb     = (const float*)d_in[3];
    const float* attn_W  = (const float*)d_in[4];
    const float* attn_b  = (const float*)d_in[5];
    const float* comb_W  = (const float*)d_in[6];
    const float* comb_b  = (const float*)d_in[7];
    const float* W_ih    = (const float*)d_in[8];
    const float* W_hh    = (const float*)d_in[9];
    const float* b_ih    = (const float*)d_in[10];
    const float* b_hh    = (const float*)d_in[11];
    const float* out_W   = (const float*)d_in[12];
    const float* out_b   = (const float*)d_in[13];

    float* out    = (float*)d_out;       // [0, V)       log-softmax
    float* h_out  = out + V;             // [V, V+H)     new hidden (scalar stores)
    float* attn_w = out + V + H;         // [V+H, V+H+F) attention weights (scalar stores)

    k_fused<<<NB, TPB>>>(tok, hidden, enc, emb, attn_W, attn_b, comb_W, comb_b,
                         W_ih, W_hh, b_ih, b_hh, out_W, out_b,
                         out, h_out, attn_w);
}